// round 13
// baseline (speedup 1.0000x reference)
#include <cuda_runtime.h>
#include <cuda_fp16.h>
#include <mma.h>
#include <math.h>
#include <stdint.h>

using namespace nvcuda;

#define B_WIN  4096
#define NT     49
#define CDIM   256
#define HEADS  8
#define HDIM   32
#define KQKV   768
#define MROWS  (B_WIN * NT)          /* 200704 = 128*1568 */
#define SCALE_F 0.17677669529663687f /* 32^-0.5 */

/* -------- scratch (allocation-free: __device__ globals) -------- */
__device__ __half g_xh[(size_t)MROWS * CDIM];    /* x in fp16            */
__device__ __half g_qkvh[(size_t)MROWS * KQKV];  /* qkv in fp16          */
__device__ __half g_oh[(size_t)MROWS * CDIM];    /* attn out in fp16     */
__device__ __half g_wh[(size_t)KQKV * CDIM];     /* qkv_w fp16           */
__device__ __half g_pwh[(size_t)CDIM * CDIM];    /* proj_w fp16          */

/* -------- cp.async helpers -------- */
__device__ __forceinline__ void cp_async16(void* smem_dst, const void* gmem_src) {
    unsigned sa = (unsigned)__cvta_generic_to_shared(smem_dst);
    asm volatile("cp.async.cg.shared.global [%0], [%1], 16;\n" :: "r"(sa), "l"(gmem_src));
}
__device__ __forceinline__ void cp_commit() {
    asm volatile("cp.async.commit_group;\n" ::: "memory");
}
template <int N>
__device__ __forceinline__ void cp_wait() {
    asm volatile("cp.async.wait_group %0;\n" :: "n"(N) : "memory");
}

/* -------- FMA-pipe exp -------- */
__device__ __forceinline__ float exp_fast(float x) {
    float y = fmaxf(x, -87.0f) * 1.44269504f;
    float t = y + 12582912.0f;                    /* 1.5*2^23 RN magic */
    int   e = __float_as_int(t) - 0x4B400000;
    float f = y - (t - 12582912.0f);
    float p =              1.33336e-3f;
    p = fmaf(p, f, 9.61813e-3f);
    p = fmaf(p, f, 5.55041e-2f);
    p = fmaf(p, f, 2.40227e-1f);
    p = fmaf(p, f, 6.93147e-1f);
    p = fmaf(p, f, 1.0f);
    return p * __int_as_float(0x3F800000 + (e << 23));
}

/* =====================================================================
 * fp32 -> fp16 convert
 * ===================================================================*/
__global__ __launch_bounds__(256) void f2h_kernel(
    const float* __restrict__ in, __half* __restrict__ out, int n)
{
    int i = (blockIdx.x * 256 + threadIdx.x) * 4;
    if (i < n) {
        float4 v = *(const float4*)&in[i];
        *(half2*)&out[i]     = __floats2half2_rn(v.x, v.y);
        *(half2*)&out[i + 2] = __floats2half2_rn(v.z, v.w);
    }
}

/* =====================================================================
 * GEMM v6 (fp16 HMMA): C[m,n] = sum_k A[m,k]*W[n,k] + bias[n]
 * Block 128(M) x 64(N), BK=64, cp.async double buffer — same tile/
 * pipeline as v5 but 256 threads = 8 warps (8M x 1N), warp tile 16x64.
 * smem 55.4 KB; __launch_bounds__(256,3) -> <=85 regs, 24 warps/SM.
 * ===================================================================*/
#define G5_STRIDE 72
#define G5_TILEH  ((128 + 64) * G5_STRIDE)
#define GEMMH_SMEM (2 * G5_TILEH * 2 + 128)

template <int OUT_HALF>
__global__ __launch_bounds__(256, 3) void gemm_h_kernel(
    const __half* __restrict__ A, const __half* __restrict__ W,
    const float* __restrict__ bias, void* __restrict__ Cv,
    int Nld, int K)
{
    extern __shared__ char smem_raw[];
    __half* Sh = (__half*)smem_raw;

    const int tid  = threadIdx.x;
    const int warp = tid >> 5;          /* 0..7, warp tile = rows warp*16.. */
    const int m0   = blockIdx.y * 128;
    const int n0   = blockIdx.x * 64;
    const int nk   = K >> 6;

    const int cr = tid >> 3;            /* base row 0..31       */
    const int cc = tid & 7;             /* 16B chunk (8 halves) */

#pragma unroll
    for (int st = 0; st < 2; st++) {
        if (st < nk) {
            int kc = st * 64;
            __half* dst = Sh + st * G5_TILEH;
#pragma unroll
            for (int i = 0; i < 4; i++) {
                int r = cr + i * 32;
                cp_async16(&dst[r * G5_STRIDE + cc * 8],
                           &A[(size_t)(m0 + r) * K + kc + cc * 8]);
            }
#pragma unroll
            for (int i = 0; i < 2; i++) {
                int r = cr + i * 32;
                cp_async16(&dst[(128 + r) * G5_STRIDE + cc * 8],
                           &W[(size_t)(n0 + r) * K + kc + cc * 8]);
            }
        }
        cp_commit();
    }

    wmma::fragment<wmma::accumulator, 16, 16, 16, float> c[4];
#pragma unroll
    for (int j = 0; j < 4; j++) wmma::fill_fragment(c[j], 0.0f);

    for (int kt = 0; kt < nk; kt++) {
        cp_wait<1>();
        __syncthreads();
        const __half* Ab = Sh + (kt & 1) * G5_TILEH;
        const __half* Bb = Ab + 128 * G5_STRIDE;

#pragma unroll
        for (int ks = 0; ks < 4; ks++) {
            wmma::fragment<wmma::matrix_a, 16, 16, 16, __half, wmma::row_major> a;
            wmma::load_matrix_sync(a, &Ab[(warp * 16) * G5_STRIDE + ks * 16],
                                   G5_STRIDE);
#pragma unroll
            for (int j = 0; j < 4; j++) {
                wmma::fragment<wmma::matrix_b, 16, 16, 16, __half, wmma::col_major> b;
                wmma::load_matrix_sync(b, &Bb[(j * 16) * G5_STRIDE + ks * 16],
                                       G5_STRIDE);
                wmma::mma_sync(c[j], a, b, c[j]);
            }
        }
        __syncthreads();

        int kn = kt + 2;
        if (kn < nk) {
            int kc = kn * 64;
            __half* dst = Sh + (kt & 1) * G5_TILEH;
#pragma unroll
            for (int i = 0; i < 4; i++) {
                int r = cr + i * 32;
                cp_async16(&dst[r * G5_STRIDE + cc * 8],
                           &A[(size_t)(m0 + r) * K + kc + cc * 8]);
            }
#pragma unroll
            for (int i = 0; i < 2; i++) {
                int r = cr + i * 32;
                cp_async16(&dst[(128 + r) * G5_STRIDE + cc * 8],
                           &W[(size_t)(n0 + r) * K + kc + cc * 8]);
            }
        }
        cp_commit();
    }

    /* staged epilogue with bias */
    float* stg = (float*)smem_raw;      /* 128 x 68 floats */
    __syncthreads();
#pragma unroll
    for (int j = 0; j < 4; j++)
        wmma::store_matrix_sync(&stg[(warp * 16) * 68 + j * 16], c[j], 68,
                                wmma::mem_row_major);
    __syncthreads();

    const int cp2 = (tid & 31) << 1;    /* fixed column pair */
    const float b0 = bias[n0 + cp2];
    const float b1 = bias[n0 + cp2 + 1];
    if (OUT_HALF) {
        __half* Ch = (__half*)Cv;
#pragma unroll
        for (int k = 0; k < 16; k++) {
            int row = (tid + k * 256) >> 5;
            *(half2*)&Ch[(size_t)(m0 + row) * Nld + n0 + cp2] =
                __floats2half2_rn(stg[row * 68 + cp2] + b0,
                                  stg[row * 68 + cp2 + 1] + b1);
        }
    } else {
        float* Cf = (float*)Cv;
#pragma unroll
        for (int k = 0; k < 16; k++) {
            int row = (tid + k * 256) >> 5;
            float2 o = make_float2(stg[row * 68 + cp2] + b0,
                                   stg[row * 68 + cp2 + 1] + b1);
            *(float2*)&Cf[(size_t)(m0 + row) * Nld + n0 + cp2] = o;
        }
    }
}

/* =====================================================================
 * Attention v7 (round-10 champion, verbatim): one block = one window x
 * TWO heads, sequential units, cp.async for both issued up front.
 * ===================================================================*/
#define AT_STR  40
#define AT_TILE (64 * AT_STR)
#define AT_UNIT (3 * AT_TILE)

__global__ __launch_bounds__(128) void attn_kernel(
    const __half* __restrict__ qkv, const float* __restrict__ mask,
    const float* __restrict__ bias_table, float* __restrict__ attn_out,
    __half* __restrict__ o_out)
{
    __shared__ __half tiles[2 * AT_UNIT];
    __shared__ float  ss[64 * 68];
    __shared__ float  biasS[2][176];
    __shared__ int    tS[64];

    const int tid  = threadIdx.x;
    const int warp = tid >> 5;
    const int h0   = blockIdx.x * 2;
    const int b    = blockIdx.y;

    const __half* wbase = qkv + (size_t)b * NT * KQKV;
#pragma unroll
    for (int u = 0; u < 2; u++) {
        const __half* hbase = wbase + (h0 + u) * HDIM;
        __half* dstu = tiles + u * AT_UNIT;
        for (int idx = tid; idx < NT * 12; idx += 128) {
            int r    = idx / 12;
            int c    = idx - r * 12;
            int seg  = c >> 2;
            int off8 = (c & 3) * 8;
            cp_async16(&dstu[seg * AT_TILE + r * AT_STR + off8],
                       &hbase[(size_t)r * KQKV + seg * 256 + off8]);
        }
        cp_commit();
    }

    {
        half2 z = __floats2half2_rn(0.f, 0.f);
        for (int i = tid; i < 2 * 15 * (AT_STR / 2); i += 128) {
            int u = i < 15 * (AT_STR / 2) ? 0 : 1;
            int j = i - u * 15 * (AT_STR / 2);
            ((half2*)(tiles + u * AT_UNIT + 2 * AT_TILE + NT * AT_STR))[j] = z;
        }
    }
    for (int r = tid; r < 169; r += 128) {
        biasS[0][r] = __ldg(&bias_table[r * HEADS + h0]);
        biasS[1][r] = __ldg(&bias_table[r * HEADS + h0 + 1]);
    }
    if (tid < 64) {
        int q7 = tid / 7;
        tS[tid] = q7 * 13 + (tid - q7 * 7);
    }

    const float* mwin = mask + (size_t)(b & 63) * NT * NT;

#pragma unroll
    for (int u = 0; u < 2; u++) {
        if (u == 0) cp_wait<1>(); else cp_wait<0>();
        __syncthreads();

        const __half* qs_ = tiles + u * AT_UNIT;
        const __half* ks_ = qs_ + AT_TILE;
        const __half* vs_ = qs_ + 2 * AT_TILE;
        __half* ps = (__half*)(tiles + u * AT_UNIT);

        /* S = Q K^T */
        {
            wmma::fragment<wmma::accumulator, 16, 16, 16, float> sc[4];
#pragma unroll
            for (int j = 0; j < 4; j++) wmma::fill_fragment(sc[j], 0.0f);
#pragma unroll
            for (int ks = 0; ks < 2; ks++) {
                wmma::fragment<wmma::matrix_a, 16, 16, 16, __half, wmma::row_major> a;
                wmma::load_matrix_sync(a, &qs_[(warp * 16) * AT_STR + ks * 16], AT_STR);
#pragma unroll
                for (int j = 0; j < 4; j++) {
                    wmma::fragment<wmma::matrix_b, 16, 16, 16, __half, wmma::col_major> bf;
                    wmma::load_matrix_sync(bf, &ks_[(j * 16) * AT_STR + ks * 16], AT_STR);
                    wmma::mma_sync(sc[j], a, bf, sc[j]);
                }
            }
#pragma unroll
            for (int j = 0; j < 4; j++)
                wmma::store_matrix_sync(&ss[(warp * 16) * 68 + j * 16], sc[j], 68,
                                        wmma::mem_row_major);
        }
        __syncthreads();

        /* attn = S*scale + bias + mask */
        {
            const float* bb = biasS[u];
            for (int idx = tid; idx < NT * NT; idx += 128) {
                int n = idx / NT, m = idx - n * NT;
                int rel = tS[n] - tS[m] + 84;
                ss[n * 68 + m] = ss[n * 68 + m] * SCALE_F + bb[rel] + mwin[idx];
            }
        }
        __syncthreads();

        /* softmax: 2 threads per row */
        {
            int n = tid >> 1, hf = tid & 1;
            float* row = &ss[n * 68];
            float mx = -1e30f;
            for (int m = hf; m < NT; m += 2) mx = fmaxf(mx, row[m]);
            mx = fmaxf(mx, __shfl_xor_sync(0xffffffffu, mx, 1));
            float sum = 0.f;
            for (int m = hf; m < NT; m += 2) {
                float e = exp_fast(row[m] - mx);
                row[m] = e;
                sum += e;
            }
            sum += __shfl_xor_sync(0xffffffffu, sum, 1);
            float inv = 1.0f / sum;
            for (int m = hf; m < NT; m += 2) row[m] *= inv;
        }
        __syncthreads();

        /* write attn probs + build fp16 P */
        {
            float* aout = attn_out + (size_t)(b * HEADS + h0 + u) * NT * NT;
            for (int idx = tid; idx < 64 * 32; idx += 128) {
                int n = idx >> 5, m2 = (idx & 31) << 1;
                float v0 = (m2     < NT) ? ss[n * 68 + m2]     : 0.f;
                float v1 = (m2 + 1 < NT) ? ss[n * 68 + m2 + 1] : 0.f;
                *(half2*)&ps[n * 72 + m2] = __floats2half2_rn(v0, v1);
                if (n < NT) {
                    if (m2     < NT) aout[n * NT + m2]     = v0;
                    if (m2 + 1 < NT) aout[n * NT + m2 + 1] = v1;
                }
            }
        }
        __syncthreads();

        /* O = P @ V */
        {
            wmma::fragment<wmma::accumulator, 16, 16, 16, float> oc[2];
#pragma unroll
            for (int j = 0; j < 2; j++) wmma::fill_fragment(oc[j], 0.0f);
#pragma unroll
            for (int ks = 0; ks < 4; ks++) {
                wmma::fragment<wmma::matrix_a, 16, 16, 16, __half, wmma::row_major> a;
                wmma::load_matrix_sync(a, &ps[(warp * 16) * 72 + ks * 16], 72);
#pragma unroll
                for (int j = 0; j < 2; j++) {
                    wmma::fragment<wmma::matrix_b, 16, 16, 16, __half, wmma::row_major> bf;
                    wmma::load_matrix_sync(bf, &vs_[(ks * 16) * AT_STR + j * 16], AT_STR);
                    wmma::mma_sync(oc[j], a, bf, oc[j]);
                }
            }
#pragma unroll
            for (int j = 0; j < 2; j++)
                wmma::store_matrix_sync(&ss[(warp * 16) * 68 + j * 16], oc[j], 68,
                                        wmma::mem_row_major);
            __syncwarp();
            __half* obase = o_out + (size_t)b * NT * CDIM + (h0 + u) * HDIM;
            int lane = tid & 31;
            for (int idx = lane; idx < 16 * 16; idx += 32) {
                int r = idx >> 4, d2 = (idx & 15) << 1, n = warp * 16 + r;
                if (n < NT)
                    *(half2*)&obase[(size_t)n * CDIM + d2] =
                        __floats2half2_rn(ss[n * 68 + d2], ss[n * 68 + d2 + 1]);
            }
        }
    }
}

/* ===================================================================*/
extern "C" void kernel_launch(void* const* d_in, const int* in_sizes, int n_in,
                              void* d_out, int out_size)
{
    const float* x          = (const float*)d_in[0];
    const float* mask       = (const float*)d_in[1];
    const float* qkv_w      = (const float*)d_in[2];
    const float* qkv_b      = (const float*)d_in[3];
    const float* proj_w     = (const float*)d_in[4];
    const float* proj_b     = (const float*)d_in[5];
    const float* bias_table = (const float*)d_in[6];

    float* out_part  = (float*)d_out;                       /* [200704][256] */
    float* attn_part = out_part + (size_t)MROWS * CDIM;     /* [32768][49][49] */

    __half *xh = nullptr, *qkvh = nullptr, *oh = nullptr, *wh = nullptr, *pwh = nullptr;
    cudaGetSymbolAddress((void**)&xh,   g_xh);
    cudaGetSymbolAddress((void**)&qkvh, g_qkvh);
    cudaGetSymbolAddress((void**)&oh,   g_oh);
    cudaGetSymbolAddress((void**)&wh,   g_wh);
    cudaGetSymbolAddress((void**)&pwh,  g_pwh);

    static int smem_set = 0;
    if (!smem_set) {
        cudaFuncSetAttribute(gemm_h_kernel<1>,
                             cudaFuncAttributeMaxDynamicSharedMemorySize, GEMMH_SMEM);
        cudaFuncSetAttribute(gemm_h_kernel<0>,
                             cudaFuncAttributeMaxDynamicSharedMemorySize, GEMMH_SMEM);
        smem_set = 1;
    }

    /* 0) fp16 conversions */
    f2h_kernel<<<(MROWS * CDIM / 4 + 255) / 256, 256>>>(x, xh, MROWS * CDIM);
    f2h_kernel<<<(KQKV * CDIM / 4 + 255) / 256, 256>>>(qkv_w, wh, KQKV * CDIM);
    f2h_kernel<<<(CDIM * CDIM / 4 + 255) / 256, 256>>>(proj_w, pwh, CDIM * CDIM);

    /* 1) QKV GEMM */
    gemm_h_kernel<1><<<dim3(KQKV / 64, MROWS / 128), 256, GEMMH_SMEM>>>(
        xh, wh, qkv_b, qkvh, KQKV, CDIM);

    /* 2) attention: one block per (window, head-pair) */
    attn_kernel<<<dim3(HEADS / 2, B_WIN), 128>>>(
        qkvh, mask, bias_table, attn_part, oh);

    /* 3) proj GEMM */
    gemm_h_kernel<0><<<dim3(CDIM / 64, MROWS / 128), 256, GEMMH_SMEM>>>(
        oh, pwh, proj_b, out_part, CDIM, CDIM);
}

// round 16
// speedup vs baseline: 1.1212x; 1.1212x over previous
#include <cuda_runtime.h>
#include <cuda_fp16.h>
#include <mma.h>
#include <math.h>
#include <stdint.h>

using namespace nvcuda;

#define B_WIN  4096
#define NT     49
#define CDIM   256
#define HEADS  8
#define HDIM   32
#define KQKV   768
#define MROWS  (B_WIN * NT)          /* 200704 = 128*1568 */
#define SCALE_F 0.17677669529663687f /* 32^-0.5 */

/* -------- scratch (allocation-free: __device__ globals) -------- */
__device__ __half g_xh[(size_t)MROWS * CDIM];    /* x in fp16            */
__device__ __half g_qkvh[(size_t)MROWS * KQKV];  /* qkv in fp16          */
__device__ __half g_oh[(size_t)MROWS * CDIM];    /* attn out in fp16     */
__device__ __half g_wh[(size_t)KQKV * CDIM];     /* qkv_w fp16           */
__device__ __half g_pwh[(size_t)CDIM * CDIM];    /* proj_w fp16          */

/* -------- cp.async helpers -------- */
__device__ __forceinline__ void cp_async16(void* smem_dst, const void* gmem_src) {
    unsigned sa = (unsigned)__cvta_generic_to_shared(smem_dst);
    asm volatile("cp.async.cg.shared.global [%0], [%1], 16;\n" :: "r"(sa), "l"(gmem_src));
}
__device__ __forceinline__ void cp_commit() {
    asm volatile("cp.async.commit_group;\n" ::: "memory");
}
template <int N>
__device__ __forceinline__ void cp_wait() {
    asm volatile("cp.async.wait_group %0;\n" :: "n"(N) : "memory");
}

/* -------- FMA-pipe exp -------- */
__device__ __forceinline__ float exp_fast(float x) {
    float y = fmaxf(x, -87.0f) * 1.44269504f;
    float t = y + 12582912.0f;                    /* 1.5*2^23 RN magic */
    int   e = __float_as_int(t) - 0x4B400000;
    float f = y - (t - 12582912.0f);
    float p =              1.33336e-3f;
    p = fmaf(p, f, 9.61813e-3f);
    p = fmaf(p, f, 5.55041e-2f);
    p = fmaf(p, f, 2.40227e-1f);
    p = fmaf(p, f, 6.93147e-1f);
    p = fmaf(p, f, 1.0f);
    return p * __int_as_float(0x3F800000 + (e << 23));
}

/* =====================================================================
 * fp32 -> fp16 convert
 * ===================================================================*/
__global__ __launch_bounds__(256) void f2h_kernel(
    const float* __restrict__ in, __half* __restrict__ out, int n)
{
    int i = (blockIdx.x * 256 + threadIdx.x) * 4;
    if (i < n) {
        float4 v = *(const float4*)&in[i];
        *(half2*)&out[i]     = __floats2half2_rn(v.x, v.y);
        *(half2*)&out[i + 2] = __floats2half2_rn(v.z, v.w);
    }
}

/* =====================================================================
 * GEMM v5 (round-9 proven config): C[m,n] = sum_k A[m,k]*W[n,k] + bias
 * Block 128x64, BK=64, cp.async double buffer, 128 thr = 4 warps,
 * warp tile 32x64 via m16n16k16 fp16->fp32, staged epilogue.
 * fp32 output path uses streaming stores (never re-read).
 * ===================================================================*/
#define G5_STRIDE 72
#define G5_TILEH  ((128 + 64) * G5_STRIDE)
#define GEMMH_SMEM (2 * G5_TILEH * 2 + 128)

template <int OUT_HALF>
__global__ __launch_bounds__(128) void gemm_h_kernel(
    const __half* __restrict__ A, const __half* __restrict__ W,
    const float* __restrict__ bias, void* __restrict__ Cv,
    int Nld, int K)
{
    extern __shared__ char smem_raw[];
    __half* Sh = (__half*)smem_raw;

    const int tid  = threadIdx.x;
    const int warp = tid >> 5;
    const int m0   = blockIdx.y * 128;
    const int n0   = blockIdx.x * 64;
    const int nk   = K >> 6;

    const int cr = tid >> 3;
    const int cc = tid & 7;

#pragma unroll
    for (int st = 0; st < 2; st++) {
        if (st < nk) {
            int kc = st * 64;
            __half* dst = Sh + st * G5_TILEH;
#pragma unroll
            for (int i = 0; i < 8; i++) {
                int r = cr + i * 16;
                cp_async16(&dst[r * G5_STRIDE + cc * 8],
                           &A[(size_t)(m0 + r) * K + kc + cc * 8]);
            }
#pragma unroll
            for (int i = 0; i < 4; i++) {
                int r = cr + i * 16;
                cp_async16(&dst[(128 + r) * G5_STRIDE + cc * 8],
                           &W[(size_t)(n0 + r) * K + kc + cc * 8]);
            }
        }
        cp_commit();
    }

    wmma::fragment<wmma::accumulator, 16, 16, 16, float> c[2][4];
#pragma unroll
    for (int i = 0; i < 2; i++)
#pragma unroll
        for (int j = 0; j < 4; j++)
            wmma::fill_fragment(c[i][j], 0.0f);

    for (int kt = 0; kt < nk; kt++) {
        cp_wait<1>();
        __syncthreads();
        const __half* Ab = Sh + (kt & 1) * G5_TILEH;
        const __half* Bb = Ab + 128 * G5_STRIDE;

#pragma unroll
        for (int ks = 0; ks < 4; ks++) {
            wmma::fragment<wmma::matrix_a, 16, 16, 16, __half, wmma::row_major> a[2];
#pragma unroll
            for (int i = 0; i < 2; i++)
                wmma::load_matrix_sync(a[i],
                    &Ab[(warp * 32 + i * 16) * G5_STRIDE + ks * 16], G5_STRIDE);
#pragma unroll
            for (int j = 0; j < 4; j++) {
                wmma::fragment<wmma::matrix_b, 16, 16, 16, __half, wmma::col_major> b;
                wmma::load_matrix_sync(b, &Bb[(j * 16) * G5_STRIDE + ks * 16], G5_STRIDE);
                wmma::mma_sync(c[0][j], a[0], b, c[0][j]);
                wmma::mma_sync(c[1][j], a[1], b, c[1][j]);
            }
        }
        __syncthreads();

        int kn = kt + 2;
        if (kn < nk) {
            int kc = kn * 64;
            __half* dst = Sh + (kt & 1) * G5_TILEH;
#pragma unroll
            for (int i = 0; i < 8; i++) {
                int r = cr + i * 16;
                cp_async16(&dst[r * G5_STRIDE + cc * 8],
                           &A[(size_t)(m0 + r) * K + kc + cc * 8]);
            }
#pragma unroll
            for (int i = 0; i < 4; i++) {
                int r = cr + i * 16;
                cp_async16(&dst[(128 + r) * G5_STRIDE + cc * 8],
                           &W[(size_t)(n0 + r) * K + kc + cc * 8]);
            }
        }
        cp_commit();
    }

    float* stg = (float*)smem_raw;
    __syncthreads();
#pragma unroll
    for (int i = 0; i < 2; i++)
#pragma unroll
        for (int j = 0; j < 4; j++)
            wmma::store_matrix_sync(&stg[(warp * 32 + i * 16) * 68 + j * 16],
                                    c[i][j], 68, wmma::mem_row_major);
    __syncthreads();

    const int cp2 = (tid & 31) << 1;
    const float b0 = bias[n0 + cp2];
    const float b1 = bias[n0 + cp2 + 1];
    if (OUT_HALF) {
        __half* Ch = (__half*)Cv;
#pragma unroll
        for (int k = 0; k < 32; k++) {
            int row = (tid + k * 128) >> 5;
            *(half2*)&Ch[(size_t)(m0 + row) * Nld + n0 + cp2] =
                __floats2half2_rn(stg[row * 68 + cp2] + b0,
                                  stg[row * 68 + cp2 + 1] + b1);
        }
    } else {
        float* Cf = (float*)Cv;
#pragma unroll
        for (int k = 0; k < 32; k++) {
            int row = (tid + k * 128) >> 5;
            float2 o = make_float2(stg[row * 68 + cp2] + b0,
                                   stg[row * 68 + cp2 + 1] + b1);
            __stwt((float2*)&Cf[(size_t)(m0 + row) * Nld + n0 + cp2], o);
        }
    }
}

/* =====================================================================
 * Attention v9 = round-10 champion + merged bias/mask/softmax phase.
 * One block = one window x TWO heads, sequential pipelined units.
 * The bias+mask pass is folded into softmax via a 25-elem register
 * array (2 threads per row), removing one 2401-elem smem pass and one
 * __syncthreads per unit. Rows >= 49 are guarded (no OOB mask/bias
 * reads); their dummy probs land only in discarded O rows.
 * attn probs written with __stwt (never re-read).
 * ===================================================================*/
#define AT_STR  40
#define AT_TILE (64 * AT_STR)
#define AT_UNIT (3 * AT_TILE)

__global__ __launch_bounds__(128) void attn_kernel(
    const __half* __restrict__ qkv, const float* __restrict__ mask,
    const float* __restrict__ bias_table, float* __restrict__ attn_out,
    __half* __restrict__ o_out)
{
    __shared__ __half tiles[2 * AT_UNIT];
    __shared__ float  ss[64 * 68];
    __shared__ float  biasS[2][176];
    __shared__ int    tS[64];

    const int tid  = threadIdx.x;
    const int warp = tid >> 5;
    const int h0   = blockIdx.x * 2;
    const int b    = blockIdx.y;

    const __half* wbase = qkv + (size_t)b * NT * KQKV;
#pragma unroll
    for (int u = 0; u < 2; u++) {
        const __half* hbase = wbase + (h0 + u) * HDIM;
        __half* dstu = tiles + u * AT_UNIT;
        for (int idx = tid; idx < NT * 12; idx += 128) {
            int r    = idx / 12;
            int c    = idx - r * 12;
            int seg  = c >> 2;
            int off8 = (c & 3) * 8;
            cp_async16(&dstu[seg * AT_TILE + r * AT_STR + off8],
                       &hbase[(size_t)r * KQKV + seg * 256 + off8]);
        }
        cp_commit();
    }

    {
        half2 z = __floats2half2_rn(0.f, 0.f);
        for (int i = tid; i < 2 * 15 * (AT_STR / 2); i += 128) {
            int u = i < 15 * (AT_STR / 2) ? 0 : 1;
            int j = i - u * 15 * (AT_STR / 2);
            ((half2*)(tiles + u * AT_UNIT + 2 * AT_TILE + NT * AT_STR))[j] = z;
        }
    }
    for (int r = tid; r < 169; r += 128) {
        biasS[0][r] = __ldg(&bias_table[r * HEADS + h0]);
        biasS[1][r] = __ldg(&bias_table[r * HEADS + h0 + 1]);
    }
    if (tid < 64) {
        int q7 = tid / 7;
        tS[tid] = q7 * 13 + (tid - q7 * 7);
    }

    const float* mwin = mask + (size_t)(b & 63) * NT * NT;

#pragma unroll
    for (int u = 0; u < 2; u++) {
        if (u == 0) cp_wait<1>(); else cp_wait<0>();
        __syncthreads();

        const __half* qs_ = tiles + u * AT_UNIT;
        const __half* ks_ = qs_ + AT_TILE;
        const __half* vs_ = qs_ + 2 * AT_TILE;
        __half* ps = (__half*)(tiles + u * AT_UNIT);

        /* S = Q K^T (raw scores staged to ss) */
        {
            wmma::fragment<wmma::accumulator, 16, 16, 16, float> sc[4];
#pragma unroll
            for (int j = 0; j < 4; j++) wmma::fill_fragment(sc[j], 0.0f);
#pragma unroll
            for (int ks = 0; ks < 2; ks++) {
                wmma::fragment<wmma::matrix_a, 16, 16, 16, __half, wmma::row_major> a;
                wmma::load_matrix_sync(a, &qs_[(warp * 16) * AT_STR + ks * 16], AT_STR);
#pragma unroll
                for (int j = 0; j < 4; j++) {
                    wmma::fragment<wmma::matrix_b, 16, 16, 16, __half, wmma::col_major> bf;
                    wmma::load_matrix_sync(bf, &ks_[(j * 16) * AT_STR + ks * 16], AT_STR);
                    wmma::mma_sync(sc[j], a, bf, sc[j]);
                }
            }
#pragma unroll
            for (int j = 0; j < 4; j++)
                wmma::store_matrix_sync(&ss[(warp * 16) * 68 + j * 16], sc[j], 68,
                                        wmma::mem_row_major);
        }
        __syncthreads();

        /* merged bias + mask + softmax: 2 threads per row, regs */
        {
            int n = tid >> 1, hf = tid & 1;
            float* row = &ss[n * 68];
            const float* bb = biasS[u];
            const bool valid = (n < NT);
            const int tn = tS[n];
            float v[25];
            float mx = -1e30f;
#pragma unroll
            for (int i = 0; i < 25; i++) {
                int m = hf + 2 * i;
                float val = -1e30f;
                if (valid && m < NT) {
                    int rel = tn - tS[m] + 84;
                    val = row[m] * SCALE_F + bb[rel] + mwin[n * NT + m];
                }
                v[i] = val;
                mx = fmaxf(mx, val);
            }
            mx = fmaxf(mx, __shfl_xor_sync(0xffffffffu, mx, 1));
            float sum = 0.f;
#pragma unroll
            for (int i = 0; i < 25; i++) {
                int m = hf + 2 * i;
                float e = (m < NT) ? exp_fast(v[i] - mx) : 0.f;
                v[i] = e;
                sum += e;
            }
            sum += __shfl_xor_sync(0xffffffffu, sum, 1);
            float inv = 1.0f / sum;
#pragma unroll
            for (int i = 0; i < 25; i++) {
                int m = hf + 2 * i;
                if (m < NT) row[m] = v[i] * inv;
            }
        }
        __syncthreads();

        /* write attn probs (streaming) + build fp16 P (cols >= 49 zeroed) */
        {
            float* aout = attn_out + (size_t)(b * HEADS + h0 + u) * NT * NT;
            for (int idx = tid; idx < 64 * 32; idx += 128) {
                int n = idx >> 5, m2 = (idx & 31) << 1;
                float v0 = (m2     < NT) ? ss[n * 68 + m2]     : 0.f;
                float v1 = (m2 + 1 < NT) ? ss[n * 68 + m2 + 1] : 0.f;
                *(half2*)&ps[n * 72 + m2] = __floats2half2_rn(v0, v1);
                if (n < NT) {
                    if (m2     < NT) __stwt(&aout[n * NT + m2],     v0);
                    if (m2 + 1 < NT) __stwt(&aout[n * NT + m2 + 1], v1);
                }
            }
        }
        __syncthreads();

        /* O = P @ V */
        {
            wmma::fragment<wmma::accumulator, 16, 16, 16, float> oc[2];
#pragma unroll
            for (int j = 0; j < 2; j++) wmma::fill_fragment(oc[j], 0.0f);
#pragma unroll
            for (int ks = 0; ks < 4; ks++) {
                wmma::fragment<wmma::matrix_a, 16, 16, 16, __half, wmma::row_major> a;
                wmma::load_matrix_sync(a, &ps[(warp * 16) * 72 + ks * 16], 72);
#pragma unroll
                for (int j = 0; j < 2; j++) {
                    wmma::fragment<wmma::matrix_b, 16, 16, 16, __half, wmma::row_major> bf;
                    wmma::load_matrix_sync(bf, &vs_[(ks * 16) * AT_STR + j * 16], AT_STR);
                    wmma::mma_sync(oc[j], a, bf, oc[j]);
                }
            }
#pragma unroll
            for (int j = 0; j < 2; j++)
                wmma::store_matrix_sync(&ss[(warp * 16) * 68 + j * 16], oc[j], 68,
                                        wmma::mem_row_major);
            __syncwarp();
            __half* obase = o_out + (size_t)b * NT * CDIM + (h0 + u) * HDIM;
            int lane = tid & 31;
            for (int idx = lane; idx < 16 * 16; idx += 32) {
                int r = idx >> 4, d2 = (idx & 15) << 1, n = warp * 16 + r;
                if (n < NT)
                    *(half2*)&obase[(size_t)n * CDIM + d2] =
                        __floats2half2_rn(ss[n * 68 + d2], ss[n * 68 + d2 + 1]);
            }
        }
    }
}

/* ===================================================================*/
extern "C" void kernel_launch(void* const* d_in, const int* in_sizes, int n_in,
                              void* d_out, int out_size)
{
    const float* x          = (const float*)d_in[0];
    const float* mask       = (const float*)d_in[1];
    const float* qkv_w      = (const float*)d_in[2];
    const float* qkv_b      = (const float*)d_in[3];
    const float* proj_w     = (const float*)d_in[4];
    const float* proj_b     = (const float*)d_in[5];
    const float* bias_table = (const float*)d_in[6];

    float* out_part  = (float*)d_out;                       /* [200704][256] */
    float* attn_part = out_part + (size_t)MROWS * CDIM;     /* [32768][49][49] */

    __half *xh = nullptr, *qkvh = nullptr, *oh = nullptr, *wh = nullptr, *pwh = nullptr;
    cudaGetSymbolAddress((void**)&xh,   g_xh);
    cudaGetSymbolAddress((void**)&qkvh, g_qkvh);
    cudaGetSymbolAddress((void**)&oh,   g_oh);
    cudaGetSymbolAddress((void**)&wh,   g_wh);
    cudaGetSymbolAddress((void**)&pwh,  g_pwh);

    static int smem_set = 0;
    if (!smem_set) {
        cudaFuncSetAttribute(gemm_h_kernel<1>,
                             cudaFuncAttributeMaxDynamicSharedMemorySize, GEMMH_SMEM);
        cudaFuncSetAttribute(gemm_h_kernel<0>,
                             cudaFuncAttributeMaxDynamicSharedMemorySize, GEMMH_SMEM);
        smem_set = 1;
    }

    /* 0) fp16 conversions */
    f2h_kernel<<<(MROWS * CDIM / 4 + 255) / 256, 256>>>(x, xh, MROWS * CDIM);
    f2h_kernel<<<(KQKV * CDIM / 4 + 255) / 256, 256>>>(qkv_w, wh, KQKV * CDIM);
    f2h_kernel<<<(CDIM * CDIM / 4 + 255) / 256, 256>>>(proj_w, pwh, CDIM * CDIM);

    /* 1) QKV GEMM */
    gemm_h_kernel<1><<<dim3(KQKV / 64, MROWS / 128), 128, GEMMH_SMEM>>>(
        xh, wh, qkv_b, qkvh, KQKV, CDIM);

    /* 2) attention: one block per (window, head-pair) */
    attn_kernel<<<dim3(HEADS / 2, B_WIN), 128>>>(
        qkvh, mask, bias_table, attn_part, oh);

    /* 3) proj GEMM */
    gemm_h_kernel<0><<<dim3(CDIM / 64, MROWS / 128), 128, GEMMH_SMEM>>>(
        oh, pwh, proj_b, out_part, CDIM, CDIM);
}